// round 1
// baseline (speedup 1.0000x reference)
#include <cuda_runtime.h>
#include <cuda_bf16.h>
#include <math_constants.h>

// Problem constants
#define B_  2
#define N_  2048
#define E_  1024
#define H_  16
#define HD_ 64
#define M_TOT   (B_ * N_)        // 4096
#define QKV_N   (3 * E_)         // 3072

// Scratch (allocation-free rule: __device__ globals)
__device__ float g_qkv[(size_t)M_TOT * QKV_N];   // [4096, 3072] ~50MB
__device__ float g_att[(size_t)M_TOT * E_];      // [4096, 1024] ~17MB

// ---------------------------------------------------------------------------
// Tiled fp32 SGEMM with bias: C[M,N] = A[M,K] @ B[K,N] + bias[N]
// BM=BN=128, BK=16, 256 threads, 8x8 register microtile.
// Assumes M%128==0, N%128==0, K%16==0 (true for all three GEMMs here).
// ---------------------------------------------------------------------------
__global__ __launch_bounds__(256, 2)
void sgemm_bias_kernel(const float* __restrict__ A,
                       const float* __restrict__ Bm,
                       const float* __restrict__ bias,
                       float* __restrict__ C,
                       int M, int N, int K)
{
    const int BM = 128, BN = 128, BK = 16;
    __shared__ float As[BK][BM];   // transposed A tile
    __shared__ float Bs[BK][BN];

    const int tid  = threadIdx.x;
    const int brow = blockIdx.y * BM;
    const int bcol = blockIdx.x * BN;
    const int ty = tid >> 4;       // 0..15
    const int tx = tid & 15;       // 0..15

    float acc[8][8];
#pragma unroll
    for (int i = 0; i < 8; i++)
#pragma unroll
        for (int j = 0; j < 8; j++) acc[i][j] = 0.f;

    for (int k0 = 0; k0 < K; k0 += BK) {
        // Load A tile: 128 rows x 16 cols = 512 float4
#pragma unroll
        for (int i = 0; i < 2; i++) {
            int idx = tid + i * 256;       // 0..511
            int row = idx >> 2;            // 0..127
            int c4  = (idx & 3) * 4;       // 0,4,8,12
            float4 v = *(const float4*)(A + (size_t)(brow + row) * K + k0 + c4);
            As[c4 + 0][row] = v.x;
            As[c4 + 1][row] = v.y;
            As[c4 + 2][row] = v.z;
            As[c4 + 3][row] = v.w;
        }
        // Load B tile: 16 rows x 128 cols = 512 float4
#pragma unroll
        for (int i = 0; i < 2; i++) {
            int idx = tid + i * 256;
            int row = idx >> 5;            // 0..15
            int c4  = (idx & 31) * 4;      // 0..124
            *(float4*)(&Bs[row][c4]) =
                *(const float4*)(Bm + (size_t)(k0 + row) * N + bcol + c4);
        }
        __syncthreads();

#pragma unroll
        for (int kk = 0; kk < BK; kk++) {
            float aF[8], bF[8];
#pragma unroll
            for (int i = 0; i < 8; i++) aF[i] = As[kk][ty * 8 + i];
#pragma unroll
            for (int j = 0; j < 8; j++) bF[j] = Bs[kk][tx * 8 + j];
#pragma unroll
            for (int i = 0; i < 8; i++)
#pragma unroll
                for (int j = 0; j < 8; j++)
                    acc[i][j] += aF[i] * bF[j];
        }
        __syncthreads();
    }

    // Epilogue with bias
#pragma unroll
    for (int i = 0; i < 8; i++) {
        size_t row = (size_t)(brow + ty * 8 + i);
#pragma unroll
        for (int j = 0; j < 8; j += 4) {
            int col = bcol + tx * 8 + j;
            float4 r;
            r.x = acc[i][j + 0] + bias[col + 0];
            r.y = acc[i][j + 1] + bias[col + 1];
            r.z = acc[i][j + 2] + bias[col + 2];
            r.w = acc[i][j + 3] + bias[col + 3];
            *(float4*)(C + row * N + col) = r;
        }
    }
}

// ---------------------------------------------------------------------------
// Flash-attention: one query per thread, 128 queries per CTA.
// qkv layout: [B*N, 3072]; per (b,n): head h owns cols [h*192, h*192+192):
//   Q = +0, K = +64, V = +128  (matches torch reshape(B,N,H,3*HD))
// Output written to g_att as [B, N, H*HD] (ready for the out-projection GEMM).
// ---------------------------------------------------------------------------
#define KT 32   // keys per tile

__global__ __launch_bounds__(128, 2)
void attention_kernel(const float* __restrict__ qkv, float* __restrict__ outp)
{
    const int b  = blockIdx.z;
    const int h  = blockIdx.y;
    const int q  = blockIdx.x * 128 + threadIdx.x;
    const int tid = threadIdx.x;

    __shared__ float Ks[KT][HD_];
    __shared__ float Vs[KT][HD_];

    const float scale = 0.125f;  // 1/sqrt(64)
    const size_t head_base = (size_t)b * N_ * QKV_N + (size_t)h * (3 * HD_);

    // Load this thread's Q row into registers (pre-scaled)
    float qreg[HD_];
    {
        const float* qp = qkv + head_base + (size_t)q * QKV_N;
#pragma unroll
        for (int d4 = 0; d4 < HD_; d4 += 4) {
            float4 v = *(const float4*)(qp + d4);
            qreg[d4 + 0] = v.x * scale;
            qreg[d4 + 1] = v.y * scale;
            qreg[d4 + 2] = v.z * scale;
            qreg[d4 + 3] = v.w * scale;
        }
    }

    float o[HD_];
#pragma unroll
    for (int d = 0; d < HD_; d++) o[d] = 0.f;
    float m = -CUDART_INF_F;
    float l = 0.f;

    for (int kt = 0; kt < N_; kt += KT) {
        __syncthreads();
        // Load K and V tiles: KT x 64 floats each = 512 float4 each
#pragma unroll
        for (int i = 0; i < 4; i++) {
            int lin = i * 128 + tid;        // 0..511
            int row = lin >> 4;             // 0..31
            int c4  = (lin & 15) * 4;       // 0..60
            const float* kp = qkv + head_base + (size_t)(kt + row) * QKV_N;
            *(float4*)(&Ks[row][c4]) = *(const float4*)(kp + HD_ + c4);
            *(float4*)(&Vs[row][c4]) = *(const float4*)(kp + 2 * HD_ + c4);
        }
        __syncthreads();

        // S = q . K^T for this tile
        float s[KT];
#pragma unroll
        for (int j = 0; j < KT; j++) {
            float acc = 0.f;
#pragma unroll
            for (int d = 0; d < HD_; d++)
                acc += qreg[d] * Ks[j][d];
            s[j] = acc;
        }

        // Online softmax update
        float tmax = s[0];
#pragma unroll
        for (int j = 1; j < KT; j++) tmax = fmaxf(tmax, s[j]);
        float newm = fmaxf(m, tmax);
        float alpha = __expf(m - newm);
        l *= alpha;
#pragma unroll
        for (int d = 0; d < HD_; d++) o[d] *= alpha;

#pragma unroll
        for (int j = 0; j < KT; j++) {
            float p = __expf(s[j] - newm);
            l += p;
#pragma unroll
            for (int d = 0; d < HD_; d++)
                o[d] += p * Vs[j][d];
        }
        m = newm;
    }

    // Write normalized output to [B, N, H*HD]
    float inv = 1.f / l;
    float* op = outp + ((size_t)b * N_ + q) * E_ + h * HD_;
#pragma unroll
    for (int d4 = 0; d4 < HD_; d4 += 4) {
        float4 r;
        r.x = o[d4 + 0] * inv;
        r.y = o[d4 + 1] * inv;
        r.z = o[d4 + 2] * inv;
        r.w = o[d4 + 3] * inv;
        *(float4*)(op + d4) = r;
    }
}

// ---------------------------------------------------------------------------
extern "C" void kernel_launch(void* const* d_in, const int* in_sizes, int n_in,
                              void* d_out, int out_size)
{
    (void)in_sizes; (void)n_in; (void)out_size;
    const float* x     = (const float*)d_in[0];
    const float* W_qkv = (const float*)d_in[1];
    const float* b_qkv = (const float*)d_in[2];
    const float* W_out = (const float*)d_in[3];
    const float* b_out = (const float*)d_in[4];
    float* out = (float*)d_out;

    float* qkv = nullptr;
    float* att = nullptr;
    cudaGetSymbolAddress((void**)&qkv, g_qkv);
    cudaGetSymbolAddress((void**)&att, g_att);

    // 1) QKV projection: [4096,1024] @ [1024,3072] + b -> g_qkv
    {
        dim3 grid(QKV_N / 128, M_TOT / 128);
        sgemm_bias_kernel<<<grid, 256>>>(x, W_qkv, b_qkv, qkv, M_TOT, QKV_N, E_);
    }
    // 2) Attention -> g_att as [B, N, E]
    {
        dim3 grid(N_ / 128, H_, B_);
        attention_kernel<<<grid, 128>>>(qkv, att);
    }
    // 3) Output projection: [4096,1024] @ [1024,1024] + b -> d_out
    {
        dim3 grid(E_ / 128, M_TOT / 128);
        sgemm_bias_kernel<<<grid, 256>>>(att, W_out, b_out, out, M_TOT, E_, E_);
    }
}

// round 2
// speedup vs baseline: 2.2386x; 2.2386x over previous
#include <cuda_runtime.h>
#include <cuda_bf16.h>
#include <stdint.h>

// Problem constants
#define B_   2
#define N_   2048
#define E_   1024
#define H_   16
#define HD_  64
#define M_TOT  (B_ * N_)     // 4096
#define QKV_N  (3 * E_)      // 3072
#define BH_    (B_ * H_)     // 32

// ---------------------------------------------------------------------------
// Device scratch (allocation-free rule)
// ---------------------------------------------------------------------------
__device__ __nv_bfloat16 g_wqkv_h[(size_t)QKV_N * E_];
__device__ __nv_bfloat16 g_wqkv_l[(size_t)QKV_N * E_];
__device__ __nv_bfloat16 g_wout_h[(size_t)E_ * E_];
__device__ __nv_bfloat16 g_wout_l[(size_t)E_ * E_];
__device__ __nv_bfloat16 g_xh[(size_t)M_TOT * E_];
__device__ __nv_bfloat16 g_xl[(size_t)M_TOT * E_];
__device__ float g_qkv[(size_t)M_TOT * QKV_N];
__device__ __nv_bfloat16 g_qh[(size_t)BH_ * N_ * HD_];
__device__ __nv_bfloat16 g_ql[(size_t)BH_ * N_ * HD_];
__device__ __nv_bfloat16 g_kh[(size_t)BH_ * N_ * HD_];
__device__ __nv_bfloat16 g_kl[(size_t)BH_ * N_ * HD_];
__device__ __nv_bfloat16 g_vth[(size_t)BH_ * HD_ * N_];
__device__ __nv_bfloat16 g_vtl[(size_t)BH_ * HD_ * N_];
__device__ __nv_bfloat16 g_oh[(size_t)M_TOT * E_];
__device__ __nv_bfloat16 g_ol[(size_t)M_TOT * E_];

// ---------------------------------------------------------------------------
// Helpers
// ---------------------------------------------------------------------------
__device__ __forceinline__ void mma16816(float c[4], const uint32_t a[4],
                                         const uint32_t b[2]) {
    asm volatile(
        "mma.sync.aligned.m16n8k16.row.col.f32.bf16.bf16.f32 "
        "{%0,%1,%2,%3},{%4,%5,%6,%7},{%8,%9},{%0,%1,%2,%3};"
        : "+f"(c[0]), "+f"(c[1]), "+f"(c[2]), "+f"(c[3])
        : "r"(a[0]), "r"(a[1]), "r"(a[2]), "r"(a[3]), "r"(b[0]), "r"(b[1]));
}

__device__ __forceinline__ void ldsm4(uint32_t r[4], const void* p) {
    uint32_t a = (uint32_t)__cvta_generic_to_shared(p);
    asm volatile("ldmatrix.sync.aligned.m8n8.x4.shared.b16 {%0,%1,%2,%3},[%4];"
                 : "=r"(r[0]), "=r"(r[1]), "=r"(r[2]), "=r"(r[3])
                 : "r"(a));
}

__device__ __forceinline__ void cpa16(void* s, const void* g) {
    uint32_t a = (uint32_t)__cvta_generic_to_shared(s);
    asm volatile("cp.async.cg.shared.global [%0],[%1],16;" ::"r"(a), "l"(g));
}

__device__ __forceinline__ float ex2f(float x) {
    float r;
    asm("ex2.approx.ftz.f32 %0,%1;" : "=f"(r) : "f"(x));
    return r;
}

__device__ __forceinline__ uint32_t packbf(float x, float y) {
    __nv_bfloat162 t;
    t.x = __float2bfloat16(x);
    t.y = __float2bfloat16(y);
    return *reinterpret_cast<uint32_t*>(&t);
}

// Split two floats into packed bf16 hi and lo pairs
__device__ __forceinline__ void split2(float x, float y, uint32_t& hi, uint32_t& lo) {
    __nv_bfloat16 xh = __float2bfloat16(x);
    __nv_bfloat16 yh = __float2bfloat16(y);
    float xr = x - __bfloat162float(xh);
    float yr = y - __bfloat162float(yh);
    __nv_bfloat162 h2, l2;
    h2.x = xh; h2.y = yh;
    l2.x = __float2bfloat16(xr); l2.y = __float2bfloat16(yr);
    hi = *reinterpret_cast<uint32_t*>(&h2);
    lo = *reinterpret_cast<uint32_t*>(&l2);
}

// ---------------------------------------------------------------------------
// 1) Elementwise split of x -> bf16 hi/lo
// ---------------------------------------------------------------------------
__global__ void split_x_kernel(const float4* __restrict__ X,
                               __nv_bfloat16* __restrict__ Xh,
                               __nv_bfloat16* __restrict__ Xl, int n4) {
    int i = blockIdx.x * blockDim.x + threadIdx.x;
    if (i >= n4) return;
    float4 v = X[i];
    uint32_t h0, l0, h1, l1;
    split2(v.x, v.y, h0, l0);
    split2(v.z, v.w, h1, l1);
    *(uint32_t*)(Xh + (size_t)i * 4)     = h0;
    *(uint32_t*)(Xh + (size_t)i * 4 + 2) = h1;
    *(uint32_t*)(Xl + (size_t)i * 4)     = l0;
    *(uint32_t*)(Xl + (size_t)i * 4 + 2) = l1;
}

// ---------------------------------------------------------------------------
// 2) Transpose + split W[K,N] -> Wt hi/lo [N,K]
// ---------------------------------------------------------------------------
__global__ void transpose_split_kernel(const float* __restrict__ W,
                                       __nv_bfloat16* __restrict__ Th,
                                       __nv_bfloat16* __restrict__ Tl,
                                       int K, int N) {
    __shared__ float t[32][33];
    int k0 = blockIdx.y * 32, n0 = blockIdx.x * 32;
    int tx = threadIdx.x & 31, ty = threadIdx.x >> 5;  // 256 thr: ty 0..7
#pragma unroll
    for (int i = 0; i < 4; i++)
        t[ty + 8 * i][tx] = W[(size_t)(k0 + ty + 8 * i) * N + n0 + tx];
    __syncthreads();
#pragma unroll
    for (int i = 0; i < 4; i++) {
        float v = t[tx][ty + 8 * i];
        __nv_bfloat16 hi = __float2bfloat16(v);
        Th[(size_t)(n0 + ty + 8 * i) * K + k0 + tx] = hi;
        Tl[(size_t)(n0 + ty + 8 * i) * K + k0 + tx] =
            __float2bfloat16(v - __bfloat162float(hi));
    }
}

// ---------------------------------------------------------------------------
// 3) Split-bf16 MMA GEMM: C[M,N] = (Ah+Al)[M,K] @ (Bh+Bl)[N,K]^T + bias
//    BM=128 BN=128 BK=16, 256 thr, 2-stage cp.async pipeline.
// ---------------------------------------------------------------------------
__global__ __launch_bounds__(256)
void gemm_split_kernel(const __nv_bfloat16* __restrict__ Ah,
                       const __nv_bfloat16* __restrict__ Al,
                       const __nv_bfloat16* __restrict__ Bh,
                       const __nv_bfloat16* __restrict__ Bl,
                       const float* __restrict__ bias,
                       float* __restrict__ C, int M, int N, int K) {
    __shared__ __nv_bfloat16 sm[2][4][128][24];  // 48KB; arr: Ah,Al,Bh,Bl
    const int tid = threadIdx.x, lane = tid & 31, w = tid >> 5;
    const int wm = w >> 2, wn = w & 3;           // 2 x 4 warp grid
    const int brow = blockIdx.y * 128, bcol = blockIdx.x * 128;

    float c[4][4][4] = {};

    auto load_stage = [&](int s, int k0) {
#pragma unroll
        for (int i = 0; i < 4; i++) {
            int ch = tid + i * 256;   // 0..1023
            int arr = ch >> 8;
            int r = (ch & 255) >> 1;
            int h8 = (ch & 1) * 8;
            const __nv_bfloat16* g;
            if (arr == 0)      g = Ah + (size_t)(brow + r) * K + k0 + h8;
            else if (arr == 1) g = Al + (size_t)(brow + r) * K + k0 + h8;
            else if (arr == 2) g = Bh + (size_t)(bcol + r) * K + k0 + h8;
            else               g = Bl + (size_t)(bcol + r) * K + k0 + h8;
            cpa16(&sm[s][arr][r][h8], g);
        }
        asm volatile("cp.async.commit_group;");
    };

    const int NIT = K >> 4;
    load_stage(0, 0);
    for (int it = 0; it < NIT; ++it) {
        if (it + 1 < NIT) {
            load_stage((it + 1) & 1, (it + 1) * 16);
            asm volatile("cp.async.wait_group 1;");
        } else {
            asm volatile("cp.async.wait_group 0;");
        }
        __syncthreads();
        int s = it & 1;
        uint32_t ah[4][4], al[4][4];
#pragma unroll
        for (int mt = 0; mt < 4; mt++) {
            int row = wm * 64 + mt * 16 + (lane & 15);
            int col = (lane >> 4) * 8;
            ldsm4(ah[mt], &sm[s][0][row][col]);
            ldsm4(al[mt], &sm[s][1][row][col]);
        }
        uint32_t bh[4][2], bl[4][2];
#pragma unroll
        for (int p = 0; p < 2; p++) {
            int row = wn * 32 + p * 16 + (lane & 15);
            int col = (lane >> 4) * 8;
            uint32_t t[4];
            ldsm4(t, &sm[s][2][row][col]);
            bh[2 * p][0] = t[0]; bh[2 * p][1] = t[2];
            bh[2 * p + 1][0] = t[1]; bh[2 * p + 1][1] = t[3];
            ldsm4(t, &sm[s][3][row][col]);
            bl[2 * p][0] = t[0]; bl[2 * p][1] = t[2];
            bl[2 * p + 1][0] = t[1]; bl[2 * p + 1][1] = t[3];
        }
#pragma unroll
        for (int mt = 0; mt < 4; mt++)
#pragma unroll
            for (int nt = 0; nt < 4; nt++) {
                mma16816(c[mt][nt], ah[mt], bh[nt]);
                mma16816(c[mt][nt], ah[mt], bl[nt]);
                mma16816(c[mt][nt], al[mt], bh[nt]);
            }
        __syncthreads();
    }

#pragma unroll
    for (int mt = 0; mt < 4; mt++) {
        int r0 = brow + wm * 64 + mt * 16 + (lane >> 2);
#pragma unroll
        for (int nt = 0; nt < 4; nt++) {
            int col = bcol + wn * 32 + nt * 8 + 2 * (lane & 3);
            float b0 = bias[col], b1 = bias[col + 1];
            float2 v0 = {c[mt][nt][0] + b0, c[mt][nt][1] + b1};
            float2 v1 = {c[mt][nt][2] + b0, c[mt][nt][3] + b1};
            *(float2*)(C + (size_t)r0 * N + col) = v0;
            *(float2*)(C + (size_t)(r0 + 8) * N + col) = v1;
        }
    }
}

// ---------------------------------------------------------------------------
// 4) Repack qkv fp32 -> per-head Q(scaled)/K bf16 hi/lo [BH,N,64],
//    V transposed hi/lo [BH,64,N]
// ---------------------------------------------------------------------------
__global__ __launch_bounds__(256)
void repack_kernel(const float* __restrict__ qkv,
                   __nv_bfloat16* __restrict__ Qh, __nv_bfloat16* __restrict__ Ql,
                   __nv_bfloat16* __restrict__ Kh, __nv_bfloat16* __restrict__ Kl,
                   __nv_bfloat16* __restrict__ Vth, __nv_bfloat16* __restrict__ Vtl) {
    __shared__ float vt[64][65];
    const int bh = blockIdx.y;
    const int b = bh >> 4, h = bh & 15;
    const int nb = blockIdx.x * 64;
    const float qscale = 0.125f * 1.4426950408889634f;  // scale * log2(e)

    for (int idx = threadIdx.x; idx < 64 * 192; idx += 256) {
        int r = idx / 192, cc = idx % 192;
        float v = qkv[(size_t)(b * N_ + nb + r) * QKV_N + h * 192 + cc];
        if (cc < 64) {
            float vq = v * qscale;
            __nv_bfloat16 hi = __float2bfloat16(vq);
            size_t o = ((size_t)bh * N_ + nb + r) * 64 + cc;
            Qh[o] = hi;
            Ql[o] = __float2bfloat16(vq - __bfloat162float(hi));
        } else if (cc < 128) {
            __nv_bfloat16 hi = __float2bfloat16(v);
            size_t o = ((size_t)bh * N_ + nb + r) * 64 + (cc - 64);
            Kh[o] = hi;
            Kl[o] = __float2bfloat16(v - __bfloat162float(hi));
        } else {
            vt[cc - 128][r] = v;
        }
    }
    __syncthreads();
    for (int idx = threadIdx.x; idx < 64 * 64; idx += 256) {
        int d = idx >> 6, nl = idx & 63;
        float v = vt[d][nl];
        __nv_bfloat16 hi = __float2bfloat16(v);
        size_t o = ((size_t)bh * 64 + d) * N_ + nb + nl;
        Vth[o] = hi;
        Vtl[o] = __float2bfloat16(v - __bfloat162float(hi));
    }
}

// ---------------------------------------------------------------------------
// 5) FA2-style attention with split-bf16 mma. 8 warps x 16 queries = 128 q/CTA.
//    Key tiles of 64. Outputs bf16 hi/lo [M_TOT, E].
// ---------------------------------------------------------------------------
__global__ __launch_bounds__(256)
void attn_kernel(const __nv_bfloat16* __restrict__ Qh, const __nv_bfloat16* __restrict__ Ql,
                 const __nv_bfloat16* __restrict__ Kh, const __nv_bfloat16* __restrict__ Kl,
                 const __nv_bfloat16* __restrict__ Vth, const __nv_bfloat16* __restrict__ Vtl,
                 __nv_bfloat16* __restrict__ Oh, __nv_bfloat16* __restrict__ Ol) {
    __shared__ __nv_bfloat16 ks[2][64][72];  // [hi/lo][key][d]
    __shared__ __nv_bfloat16 vs[2][64][72];  // [hi/lo][d][key]
    const int tid = threadIdx.x, lane = tid & 31, w = tid >> 5;
    const int bh = blockIdx.y, qb = blockIdx.x;
    const size_t qkbase = (size_t)bh * N_ * 64;
    const size_t vbase = (size_t)bh * 64 * N_;

    // Q fragments (held in registers for the whole kernel)
    uint32_t qh[4][4], ql[4][4];
    {
        int r0 = qb * 128 + w * 16 + (lane >> 2);
        int c0 = 2 * (lane & 3);
#pragma unroll
        for (int kd = 0; kd < 4; kd++) {
            const __nv_bfloat16* ph = Qh + qkbase + (size_t)r0 * 64 + kd * 16 + c0;
            const __nv_bfloat16* pl = Ql + qkbase + (size_t)r0 * 64 + kd * 16 + c0;
            qh[kd][0] = *(const uint32_t*)(ph);
            qh[kd][1] = *(const uint32_t*)(ph + 8 * 64);
            qh[kd][2] = *(const uint32_t*)(ph + 8);
            qh[kd][3] = *(const uint32_t*)(ph + 8 * 64 + 8);
            ql[kd][0] = *(const uint32_t*)(pl);
            ql[kd][1] = *(const uint32_t*)(pl + 8 * 64);
            ql[kd][2] = *(const uint32_t*)(pl + 8);
            ql[kd][3] = *(const uint32_t*)(pl + 8 * 64 + 8);
        }
    }

    float m0 = -1e30f, m1 = -1e30f, l0 = 0.f, l1 = 0.f;
    float o[8][4] = {};

    for (int kt0 = 0; kt0 < N_; kt0 += 64) {
        __syncthreads();
#pragma unroll
        for (int i = 0; i < 8; i++) {
            int ch = tid + i * 256;  // 0..2047
            int arr = ch >> 9;
            int r = (ch & 511) >> 3;
            int h8 = (ch & 7) * 8;
            if (arr == 0)
                *(float4*)&ks[0][r][h8] = *(const float4*)(Kh + qkbase + (size_t)(kt0 + r) * 64 + h8);
            else if (arr == 1)
                *(float4*)&ks[1][r][h8] = *(const float4*)(Kl + qkbase + (size_t)(kt0 + r) * 64 + h8);
            else if (arr == 2)
                *(float4*)&vs[0][r][h8] = *(const float4*)(Vth + vbase + (size_t)r * N_ + kt0 + h8);
            else
                *(float4*)&vs[1][r][h8] = *(const float4*)(Vtl + vbase + (size_t)r * N_ + kt0 + h8);
        }
        __syncthreads();

        // S = Q K^T (pre-scaled, log2 domain)
        float s[8][4] = {};
#pragma unroll
        for (int kd = 0; kd < 4; kd++) {
            uint32_t kbh[8][2], kbl[8][2];
#pragma unroll
            for (int p = 0; p < 4; p++) {
                int row = p * 16 + (lane & 15);
                int col = kd * 16 + (lane >> 4) * 8;
                uint32_t t[4];
                ldsm4(t, &ks[0][row][col]);
                kbh[2 * p][0] = t[0]; kbh[2 * p][1] = t[2];
                kbh[2 * p + 1][0] = t[1]; kbh[2 * p + 1][1] = t[3];
                ldsm4(t, &ks[1][row][col]);
                kbl[2 * p][0] = t[0]; kbl[2 * p][1] = t[2];
                kbl[2 * p + 1][0] = t[1]; kbl[2 * p + 1][1] = t[3];
            }
#pragma unroll
            for (int nt = 0; nt < 8; nt++) {
                mma16816(s[nt], qh[kd], kbh[nt]);
                mma16816(s[nt], qh[kd], kbl[nt]);
                mma16816(s[nt], ql[kd], kbh[nt]);
            }
        }

        // Online softmax (base-2)
        float mx0 = -1e30f, mx1 = -1e30f;
#pragma unroll
        for (int nt = 0; nt < 8; nt++) {
            mx0 = fmaxf(mx0, fmaxf(s[nt][0], s[nt][1]));
            mx1 = fmaxf(mx1, fmaxf(s[nt][2], s[nt][3]));
        }
        mx0 = fmaxf(mx0, __shfl_xor_sync(0xffffffffu, mx0, 1));
        mx0 = fmaxf(mx0, __shfl_xor_sync(0xffffffffu, mx0, 2));
        mx1 = fmaxf(mx1, __shfl_xor_sync(0xffffffffu, mx1, 1));
        mx1 = fmaxf(mx1, __shfl_xor_sync(0xffffffffu, mx1, 2));
        float mn0 = fmaxf(m0, mx0), mn1 = fmaxf(m1, mx1);
        float a0 = ex2f(m0 - mn0), a1 = ex2f(m1 - mn1);
        m0 = mn0; m1 = mn1;

        float sum0 = 0.f, sum1 = 0.f;
#pragma unroll
        for (int nt = 0; nt < 8; nt++) {
            s[nt][0] = ex2f(s[nt][0] - mn0);
            s[nt][1] = ex2f(s[nt][1] - mn0);
            s[nt][2] = ex2f(s[nt][2] - mn1);
            s[nt][3] = ex2f(s[nt][3] - mn1);
            sum0 += s[nt][0] + s[nt][1];
            sum1 += s[nt][2] + s[nt][3];
        }
        sum0 += __shfl_xor_sync(0xffffffffu, sum0, 1);
        sum0 += __shfl_xor_sync(0xffffffffu, sum0, 2);
        sum1 += __shfl_xor_sync(0xffffffffu, sum1, 1);
        sum1 += __shfl_xor_sync(0xffffffffu, sum1, 2);
        l0 = l0 * a0 + sum0;
        l1 = l1 * a1 + sum1;
#pragma unroll
        for (int nd = 0; nd < 8; nd++) {
            o[nd][0] *= a0; o[nd][1] *= a0;
            o[nd][2] *= a1; o[nd][3] *= a1;
        }

        // P fragments (split hi/lo)
        uint32_t pah[4][4], pal[4][4];
#pragma unroll
        for (int kt = 0; kt < 4; kt++) {
            split2(s[2 * kt][0], s[2 * kt][1], pah[kt][0], pal[kt][0]);
            split2(s[2 * kt][2], s[2 * kt][3], pah[kt][1], pal[kt][1]);
            split2(s[2 * kt + 1][0], s[2 * kt + 1][1], pah[kt][2], pal[kt][2]);
            split2(s[2 * kt + 1][2], s[2 * kt + 1][3], pah[kt][3], pal[kt][3]);
        }

        // O += P V
#pragma unroll
        for (int kt = 0; kt < 4; kt++) {
            uint32_t vbh[8][2], vbl[8][2];
#pragma unroll
            for (int p = 0; p < 4; p++) {
                int row = p * 16 + (lane & 15);
                int col = kt * 16 + (lane >> 4) * 8;
                uint32_t t[4];
                ldsm4(t, &vs[0][row][col]);
                vbh[2 * p][0] = t[0]; vbh[2 * p][1] = t[2];
                vbh[2 * p + 1][0] = t[1]; vbh[2 * p + 1][1] = t[3];
                ldsm4(t, &vs[1][row][col]);
                vbl[2 * p][0] = t[0]; vbl[2 * p][1] = t[2];
                vbl[2 * p + 1][0] = t[1]; vbl[2 * p + 1][1] = t[3];
            }
#pragma unroll
            for (int nd = 0; nd < 8; nd++) {
                mma16816(o[nd], pah[kt], vbh[nd]);
                mma16816(o[nd], pah[kt], vbl[nd]);
                mma16816(o[nd], pal[kt], vbh[nd]);
            }
        }
    }

    // Epilogue: normalize, split to bf16 hi/lo, write [M_TOT, E]
    float i0 = 1.f / l0, i1 = 1.f / l1;
    int b = bh >> 4, h = bh & 15;
    int r0 = b * N_ + qb * 128 + w * 16 + (lane >> 2);
#pragma unroll
    for (int nd = 0; nd < 8; nd++) {
        int col = h * 64 + nd * 8 + 2 * (lane & 3);
        uint32_t hi, lo;
        split2(o[nd][0] * i0, o[nd][1] * i0, hi, lo);
        *(uint32_t*)(Oh + (size_t)r0 * E_ + col) = hi;
        *(uint32_t*)(Ol + (size_t)r0 * E_ + col) = lo;
        split2(o[nd][2] * i1, o[nd][3] * i1, hi, lo);
        *(uint32_t*)(Oh + (size_t)(r0 + 8) * E_ + col) = hi;
        *(uint32_t*)(Ol + (size_t)(r0 + 8) * E_ + col) = lo;
    }
}

// ---------------------------------------------------------------------------
extern "C" void kernel_launch(void* const* d_in, const int* in_sizes, int n_in,
                              void* d_out, int out_size) {
    (void)in_sizes; (void)n_in; (void)out_size;
    const float* x     = (const float*)d_in[0];
    const float* W_qkv = (const float*)d_in[1];
    const float* b_qkv = (const float*)d_in[2];
    const float* W_out = (const float*)d_in[3];
    const float* b_out = (const float*)d_in[4];
    float* out = (float*)d_out;

    __nv_bfloat16 *wqh, *wql, *woh, *wol, *xh, *xl;
    __nv_bfloat16 *q_h, *q_l, *k_h, *k_l, *vt_h, *vt_l, *o_h, *o_l;
    float* qkv;
    cudaGetSymbolAddress((void**)&wqh, g_wqkv_h);
    cudaGetSymbolAddress((void**)&wql, g_wqkv_l);
    cudaGetSymbolAddress((void**)&woh, g_wout_h);
    cudaGetSymbolAddress((void**)&wol, g_wout_l);
    cudaGetSymbolAddress((void**)&xh, g_xh);
    cudaGetSymbolAddress((void**)&xl, g_xl);
    cudaGetSymbolAddress((void**)&qkv, g_qkv);
    cudaGetSymbolAddress((void**)&q_h, g_qh);
    cudaGetSymbolAddress((void**)&q_l, g_ql);
    cudaGetSymbolAddress((void**)&k_h, g_kh);
    cudaGetSymbolAddress((void**)&k_l, g_kl);
    cudaGetSymbolAddress((void**)&vt_h, g_vth);
    cudaGetSymbolAddress((void**)&vt_l, g_vtl);
    cudaGetSymbolAddress((void**)&o_h, g_oh);
    cudaGetSymbolAddress((void**)&o_l, g_ol);

    // Prep: split x, transpose+split weights
    split_x_kernel<<<(M_TOT * E_ / 4 + 255) / 256, 256>>>((const float4*)x, xh, xl,
                                                          M_TOT * E_ / 4);
    transpose_split_kernel<<<dim3(QKV_N / 32, E_ / 32), 256>>>(W_qkv, wqh, wql, E_, QKV_N);
    transpose_split_kernel<<<dim3(E_ / 32, E_ / 32), 256>>>(W_out, woh, wol, E_, E_);

    // QKV projection
    gemm_split_kernel<<<dim3(QKV_N / 128, M_TOT / 128), 256>>>(
        xh, xl, wqh, wql, b_qkv, qkv, M_TOT, QKV_N, E_);

    // Repack into per-head layouts
    repack_kernel<<<dim3(N_ / 64, BH_), 256>>>(qkv, q_h, q_l, k_h, k_l, vt_h, vt_l);

    // Attention
    attn_kernel<<<dim3(N_ / 128, BH_), 256>>>(q_h, q_l, k_h, k_l, vt_h, vt_l, o_h, o_l);

    // Output projection
    gemm_split_kernel<<<dim3(E_ / 128, M_TOT / 128), 256>>>(
        o_h, o_l, woh, wol, b_out, out, M_TOT, E_, E_);
}